// round 1
// baseline (speedup 1.0000x reference)
#include <cuda_runtime.h>
#include <math.h>

// Problem constants
#define SS   4096
#define BB   16
#define CC   512
#define TMAX 512

// ---------------- device scratch (static allocation; no cudaMalloc) ----------------
__device__ float g_alpha[BB * SS];          // scaled alpha
__device__ float g_csum [BB * SS];          // fp32 assoc-scan cumsum
__device__ int   g_f    [BB * SS];          // floor(csum + 1e-4)
__device__ float g_feats[BB * TMAX * 512];  // feats, K padded to 512 (col 511 = 0)
__device__ float g_Wp   [512 * 512];        // W padded to 512x512 (col 511 = 0)

// level offsets for the 4096-element associative-scan buffers in smem
__constant__ int c_off[13] = {0,4096,6144,7168,7680,7936,8064,8128,8160,8176,8184,8188,8190};

// ---------------- Phase 1: alpha, alpha_sum, exact JAX-tree cumsum, fire indices ----
__device__ __forceinline__ void downsweep(float* sb, int tid) {
    for (int l = 1; l <= 12; l++) {
        int sz = SS >> l;
        int o  = c_off[l], oi = c_off[l-1];
        for (int i = tid; i < sz; i += 512)
            sb[o + i] = sb[oi + 2*i] + sb[oi + 2*i + 1];
        __syncthreads();
    }
}

__device__ __forceinline__ void upsweep(float* sb, int tid) {
    // scan at level 12 is the single total itself
    for (int l = 11; l >= 0; l--) {
        int sz = SS >> l;
        int o  = c_off[l], ou = c_off[l+1];
        for (int i = tid; i < sz; i += 512) {
            float v;
            if (i & 1)          v = sb[ou + (i >> 1)];
            else if (i == 0)    v = sb[o];
            else                v = sb[ou + (i >> 1) - 1] + sb[o + i];
            sb[o + i] = v;
        }
        __syncthreads();
    }
}

__global__ __launch_bounds__(512)
void phase1_kernel(const float* __restrict__ x,
                   const unsigned char* __restrict__ mask,
                   const int* __restrict__ tl,
                   float* __restrict__ alpha_sum_out) {
    __shared__ float sb[8192];
    int b   = blockIdx.x;
    int tid = threadIdx.x;

    // raw alpha = sigmoid(mask ? -1e4 : x[s,b,C-1]); double-precision sigmoid for fidelity
    for (int s = tid; s < SS; s += 512) {
        float a = mask[b * SS + s] ? -10000.0f : x[(size_t)s * (BB*CC) + b * CC + (CC - 1)];
        double sg = 1.0 / (1.0 + exp(-(double)a));
        sb[s] = (float)sg;
    }
    __syncthreads();

    // tree reduce for alpha_sum
    downsweep(sb, tid);
    float asum = sb[c_off[12]];
    if (tid == 0) alpha_sum_out[b] = asum;
    float tlf = (float)tl[b];
    __syncthreads();

    // scale: ((alpha * BETA) * tl) / alpha_sum   (BETA = 1.0 exact)
    for (int s = tid; s < SS; s += 512) {
        float sc = (sb[s] * tlf) / asum;
        sb[s] = sc;
        g_alpha[b * SS + s] = sc;
    }
    __syncthreads();

    // exact JAX associative_scan tree (fp32)
    downsweep(sb, tid);
    upsweep(sb, tid);

    for (int s = tid; s < SS; s += 512) {
        float c = sb[s];
        g_csum[b * SS + s] = c;
        g_f  [b * SS + s] = (int)floorf(c + 1e-4f);
    }
}

// ---------------- Phase 1b: pad W (512,511) -> g_Wp (512,512), col 511 = 0 ----------
__global__ void prep_w_kernel(const float* __restrict__ W) {
    int i = blockIdx.x * 256 + threadIdx.x;
    if (i < 512 * 512) {
        int k = i & 511;
        int n = i >> 9;
        g_Wp[i] = (k < 511) ? W[n * 511 + k] : 0.0f;
    }
}

// ---------------- Phase 2: sparse gather  feats[b,t,:] = sum_s w(b,t,s) x[s,b,:511] --
__global__ __launch_bounds__(128)
void gather_kernel(const float* __restrict__ x) {
    int bt = blockIdx.x;            // b*512 + t
    int b  = bt >> 9;
    int t  = bt & 511;
    const int*   f  = g_f     + b * SS;
    const float* al = g_alpha + b * SS;
    const float* cs = g_csum  + b * SS;

    // window: lo = first s with f[s] >= t-1 ; hi = min(first s with f[s] > t, S-1)
    int lo, hi;
    {
        int l = 0, r = SS;
        while (l < r) { int m = (l + r) >> 1; if (f[m] >= t - 1) r = m; else l = m + 1; }
        lo = l;
        l = 0; r = SS;
        while (l < r) { int m = (l + r) >> 1; if (f[m] > t) r = m; else l = m + 1; }
        hi = (l < SS - 1) ? l : SS - 1;
    }

    __shared__ float wbuf[128];
    int tid = threadIdx.x;
    int c0  = tid * 4;
    float4 acc = make_float4(0.f, 0.f, 0.f, 0.f);

    for (int base = lo; base <= hi; base += 128) {
        int s = base + tid;
        float w = 0.f;
        if (s <= hi) {
            int   d1   = f[s];
            int   d0   = (s == 0) ? 0 : f[s - 1];
            int   fire = d1 - d0;
            float a    = al[s];
            float c    = cs[s];
            float ex   = (fire > 1) ? (float)(fire - 1) : 0.f;
            float rw   = (fire > 0) ? (c - (float)d1) : a;
            float lw   = (a - rw) - ex;
            if (d1 == t) w += rw;
            if (d0 == t) w += lw;
            int ei = d0 + 1; if (ei > TMAX - 1) ei = TMAX - 1;
            if (ei == t) w += fminf(ex, 1.0f);
            if (t >= d0 + 2 && t < d1) w = 1.0f;   // fill overwrite (no overlap by construction)
        }
        wbuf[tid] = w;
        __syncthreads();

        int n = hi - base + 1; if (n > 128) n = 128;
        const float* xp = x + (size_t)base * (BB*CC) + b * CC + c0;
        for (int j = 0; j < n; j++) {
            float wj = wbuf[j];
            if (wj != 0.f) {
                float4 v = *(const float4*)(xp + (size_t)j * (BB*CC));
                acc.x += wj * v.x; acc.y += wj * v.y;
                acc.z += wj * v.z; acc.w += wj * v.w;
            }
        }
        __syncthreads();
    }

    if (c0 == 508) acc.w = 0.f;   // channel 511 is the alpha channel: excluded (pad = 0)
    *(float4*)(g_feats + (size_t)bt * 512 + c0) = acc;
}

// ---------------- Phase 3: fp32 GEMM  out[m,n] = feats[m,:] . Wp[n,:] + bias[n] -----
// M=8192, N=512, K=512. BM=BN=128, BK=16, 256 threads, 8x8 per thread.
#define BM 128
#define BN 128
#define BK 16
#define PAD 4

__global__ __launch_bounds__(256)
void gemm_kernel(const float* __restrict__ bias, float* __restrict__ out) {
    __shared__ float As[BK][BM + PAD];
    __shared__ float Bs[BK][BN + PAD];

    int bm  = blockIdx.x * BM;
    int bn  = blockIdx.y * BN;
    int tid = threadIdx.x;
    int tx  = tid & 15;
    int ty  = tid >> 4;

    float acc[8][8];
    #pragma unroll
    for (int i = 0; i < 8; i++)
        #pragma unroll
        for (int j = 0; j < 8; j++) acc[i][j] = 0.f;

    for (int k0 = 0; k0 < 512; k0 += BK) {
        // load A tile (g_feats): 128 rows x 16 k = 512 float4, 2 per thread
        #pragma unroll
        for (int r = 0; r < 2; r++) {
            int fi  = tid + 256 * r;
            int row = fi >> 2;
            int kk  = (fi & 3) * 4;
            float4 v = *(const float4*)(g_feats + (size_t)(bm + row) * 512 + k0 + kk);
            As[kk + 0][row] = v.x; As[kk + 1][row] = v.y;
            As[kk + 2][row] = v.z; As[kk + 3][row] = v.w;
        }
        // load W tile (g_Wp, padded 512 stride)
        #pragma unroll
        for (int r = 0; r < 2; r++) {
            int fi  = tid + 256 * r;
            int row = fi >> 2;
            int kk  = (fi & 3) * 4;
            float4 v = *(const float4*)(g_Wp + (size_t)(bn + row) * 512 + k0 + kk);
            Bs[kk + 0][row] = v.x; Bs[kk + 1][row] = v.y;
            Bs[kk + 2][row] = v.z; Bs[kk + 3][row] = v.w;
        }
        __syncthreads();

        #pragma unroll
        for (int kk = 0; kk < BK; kk++) {
            float af[8], bf[8];
            #pragma unroll
            for (int i = 0; i < 8; i++) af[i] = As[kk][ty * 8 + i];
            #pragma unroll
            for (int j = 0; j < 8; j++) bf[j] = Bs[kk][tx * 8 + j];
            #pragma unroll
            for (int i = 0; i < 8; i++)
                #pragma unroll
                for (int j = 0; j < 8; j++)
                    acc[i][j] += af[i] * bf[j];
        }
        __syncthreads();
    }

    float bv[8];
    #pragma unroll
    for (int j = 0; j < 8; j++) bv[j] = bias[bn + tx * 8 + j];

    // out layout: (T, B, C): idx = t*(B*C) + b*C + n, with m = b*512 + t
    #pragma unroll
    for (int i = 0; i < 8; i++) {
        int m  = bm + ty * 8 + i;
        int b  = m >> 9;
        int t  = m & 511;
        float* op = out + (size_t)t * (BB * CC) + b * CC + bn + tx * 8;
        #pragma unroll
        for (int j = 0; j < 8; j += 4) {
            float4 v;
            v.x = acc[i][j + 0] + bv[j + 0];
            v.y = acc[i][j + 1] + bv[j + 1];
            v.z = acc[i][j + 2] + bv[j + 2];
            v.w = acc[i][j + 3] + bv[j + 3];
            *(float4*)(op + j) = v;
        }
    }
}

// ---------------- launch ------------------------------------------------------------
extern "C" void kernel_launch(void* const* d_in, const int* in_sizes, int n_in,
                              void* d_out, int out_size) {
    const float*         x    = (const float*)d_in[0];
    const unsigned char* mask = (const unsigned char*)d_in[1];
    const int*           tl   = (const int*)d_in[2];
    const float*         W    = (const float*)d_in[3];
    const float*         bias = (const float*)d_in[4];
    float*               out  = (float*)d_out;

    // alpha_sum tail lives after the (T, B, C) main output
    float* asum_out = out + (size_t)TMAX * BB * CC;

    phase1_kernel<<<BB, 512>>>(x, mask, tl, asum_out);
    prep_w_kernel<<<(512 * 512 + 255) / 256, 256>>>(W);
    gather_kernel<<<BB * TMAX, 128>>>(x);
    gemm_kernel<<<dim3(8192 / BM, 512 / BN), 256>>>(bias, out);
}